// round 2
// baseline (speedup 1.0000x reference)
#include <cuda_runtime.h>
#include <cuda_bf16.h>
#include <cstdint>

// Problem constants (fixed by the reference):
//   N = 400 nodes, E = N*(N-1) = 159600 edges, B = 32 batch.
// Output: [B, E, 2] f32. out[b,e,:] = adj[i,j]!=0 ? (0,1) : (1,0)
// where edge e -> (i = e/399, j = r + (r>=i)), r = e%399  (np.where(~eye) order).
//
// Pure store-bandwidth kernel: one thread writes one float4 = 2 edges' one-hot
// pairs. Grid: x over edge pairs (E/2 = 79800), y over batch (32).

#define N_NODES 400
#define N_M1    399
#define N_EDGES 159600          // 400*399
#define E_PAIRS 79800           // N_EDGES / 2
#define BATCH   32

__global__ __launch_bounds__(256)
void edge_onehot_kernel(const float* __restrict__ adj, float4* __restrict__ out)
{
    const int p = blockIdx.x * blockDim.x + threadIdx.x;   // edge-pair index
    if (p >= E_PAIRS) return;
    const int b = blockIdx.y;

    const int e0 = 2 * p;
    const int e1 = e0 + 1;

    // edge -> (send i, rec j)
    int i0 = e0 / N_M1;
    int r0 = e0 - i0 * N_M1;
    int j0 = r0 + (r0 >= i0 ? 1 : 0);

    int i1 = e1 / N_M1;
    int r1 = e1 - i1 * N_M1;
    int j1 = r1 + (r1 >= i1 ? 1 : 0);

    const float a0 = __ldg(&adj[i0 * N_NODES + j0]);
    const float a1 = __ldg(&adj[i1 * N_NODES + j1]);

    const float t0 = (a0 != 0.0f) ? 1.0f : 0.0f;
    const float t1 = (a1 != 0.0f) ? 1.0f : 0.0f;

    // out[b, e, :] pairs: (1-t, t)
    float4 v;
    v.x = 1.0f - t0;
    v.y = t0;
    v.z = 1.0f - t1;
    v.w = t1;

    // float4 index within full output: batch stride = N_EDGES float2 = E_PAIRS float4... careful:
    // per batch there are N_EDGES*2 floats = N_EDGES float2 = 79800*4 floats -> as float4: N_EDGES*2/4 = 79800 float4.
    out[(size_t)b * E_PAIRS + p] = v;
}

extern "C" void kernel_launch(void* const* d_in, const int* in_sizes, int n_in,
                              void* d_out, int out_size)
{
    // metadata order: inputs, weather, rel_rec, rel_send, adj_matrix
    const float* adj = (const float*)d_in[4];
    float4* out = (float4*)d_out;

    dim3 block(256);
    dim3 grid((E_PAIRS + 255) / 256, BATCH);   // (312, 32)
    edge_onehot_kernel<<<grid, block>>>(adj, out);
}

// round 3
// speedup vs baseline: 1.3381x; 1.3381x over previous
#include <cuda_runtime.h>
#include <cuda_bf16.h>
#include <cstdint>

// N = 400 nodes, E = N*(N-1) = 159600 edges, B = 32 batch.
// Output [B, E, 2] f32: out[b,e,:] = adj[i,j]!=0 ? (0,1) : (1,0),
// edge e -> (i = e/399, j = r + (r>=i)), r = e%399  (np.where(~eye) order).
//
// Key fact: output is batch-invariant. Each thread computes one float4
// (= 2 edges) ONCE and stores it to BPT batches (strided), killing the 32x
// redundant load/ALU work of the naive version. Kernel is then bounded by
// STG.128 issue + L2 write throughput (~3.4us floor each).

#define N_NODES 400
#define N_M1    399
#define N_EDGES 159600
#define E_PAIRS 79800           // float4 elements per batch
#define BATCH   32
#define BPT     8               // batches per thread
#define GRID_Y  (BATCH / BPT)   // 4

__global__ __launch_bounds__(256)
void edge_onehot_bcast_kernel(const float* __restrict__ adj, float4* __restrict__ out)
{
    const int p = blockIdx.x * blockDim.x + threadIdx.x;   // edge-pair index
    if (p >= E_PAIRS) return;

    const int e0 = 2 * p;
    const int e1 = e0 + 1;

    // edge -> (send i, rec j); /399 becomes mul-hi+shift (constant division)
    int i0 = e0 / N_M1;
    int r0 = e0 - i0 * N_M1;
    int j0 = r0 + (r0 >= i0 ? 1 : 0);

    int i1 = e1 / N_M1;
    int r1 = e1 - i1 * N_M1;
    int j1 = r1 + (r1 >= i1 ? 1 : 0);

    const float a0 = __ldg(&adj[i0 * N_NODES + j0]);
    const float a1 = __ldg(&adj[i1 * N_NODES + j1]);

    const float t0 = (a0 != 0.0f) ? 1.0f : 0.0f;
    const float t1 = (a1 != 0.0f) ? 1.0f : 0.0f;

    float4 v;
    v.x = 1.0f - t0;
    v.y = t0;
    v.z = 1.0f - t1;
    v.w = t1;

    // Broadcast to BPT batches: addresses strided by E_PAIRS float4s.
    const int b0 = blockIdx.y * BPT;
    float4* dst = out + (size_t)b0 * E_PAIRS + p;
#pragma unroll
    for (int k = 0; k < BPT; ++k) {
        dst[(size_t)k * E_PAIRS] = v;
    }
}

extern "C" void kernel_launch(void* const* d_in, const int* in_sizes, int n_in,
                              void* d_out, int out_size)
{
    // metadata order: inputs, weather, rel_rec, rel_send, adj_matrix
    const float* adj = (const float*)d_in[4];
    float4* out = (float4*)d_out;

    dim3 block(256);
    dim3 grid((E_PAIRS + 255) / 256, GRID_Y);   // (312, 4)
    edge_onehot_bcast_kernel<<<grid, block>>>(adj, out);
}